// round 1
// baseline (speedup 1.0000x reference)
#include <cuda_runtime.h>

typedef unsigned long long u64;
#define DI __device__ __forceinline__

// Fixed average-trace buffer (length 120) from the reference module
__constant__ float c_avg[120] = {
 0.0256f,0.0823f,0.1157f,0.1315f,0.1366f,0.1369f,0.1347f,0.1308f,0.1259f,0.1205f,
 0.1146f,0.1086f,0.1028f,0.0970f,0.0913f,0.0858f,0.0805f,0.0756f,0.0708f,0.0664f,
 0.0623f,0.0584f,0.0549f,0.0515f,0.0485f,0.0456f,0.0429f,0.0404f,0.0381f,0.0360f,
 0.0340f,0.0321f,0.0304f,0.0287f,0.0272f,0.0258f,0.0245f,0.0233f,0.0222f,0.0211f,
 0.0201f,0.0191f,0.0182f,0.0173f,0.0165f,0.0158f,0.0150f,0.0143f,0.0137f,0.0130f,
 0.0125f,0.0119f,0.0114f,0.0108f,0.0104f,0.0099f,0.0095f,0.0091f,0.0087f,0.0083f,
 0.0080f,0.0077f,0.0074f,0.0071f,0.0068f,0.0065f,0.0062f,0.0060f,0.0058f,0.0055f,
 0.0053f,0.0050f,0.0049f,0.0047f,0.0045f,0.0044f,0.0042f,0.0040f,0.0039f,0.0038f,
 0.0036f,0.0034f,0.0033f,0.0032f,0.0031f,0.0030f,0.0029f,0.0028f,0.0027f,0.0026f,
 0.0025f,0.0024f,0.0023f,0.0022f,0.0021f,0.0021f,0.0020f,0.0019f,0.0018f,0.0018f,
 0.0017f,0.0017f,0.0016f,0.0016f,0.0015f,0.0015f,0.0014f,0.0014f,0.0013f,0.0013f,
 0.0013f,0.0012f,0.0012f,0.0011f,0.0011f,0.0011f,0.0010f,0.0010f,0.0010f,0.0009f
};

DI u64 pk2(float lo, float hi){ u64 r; asm("mov.b64 %0, {%1,%2};" : "=l"(r) : "f"(lo), "f"(hi)); return r; }
DI void up2(u64 v, float& lo, float& hi){ asm("mov.b64 {%0,%1}, %2;" : "=f"(lo), "=f"(hi) : "l"(v)); }
// Packed dual fp32 FMA (Blackwell f32x2 path: 2 FMAs per issue)
DI u64 ffma2(u64 a, u64 b, u64 c){ u64 d; asm("fma.rn.f32x2 %0, %1, %2, %3;" : "=l"(d) : "l"(a), "l"(b), "l"(c)); return d; }
DI float sigf(float x){ return __fdividef(1.0f, 1.0f + __expf(-x)); }
DI float tanx(float x){ float t = __expf(-2.0f*x); return __fdividef(1.0f - t, 1.0f + t); }

// Shared memory layout (bytes)
#define OFF_BASE2 0        // u64 base2[60][128]      : 61440  (per-seq input projection, packed gate pairs)
#define OFF_WHH   61440    // ulonglong2 whh[30][30]  : 14400  (w_hh1 packed: [k][m] -> gates 4m..4m+3)
#define OFF_W13   75840    // u64 w13p[60]            : 480    (trace-channel column of w_ih1, packed)
#define OFF_WI2   76320    // u64 wi2p[30][2]         : 480    (layer-2 input weights, packed q-pairs)
#define OFF_WI1   76800    // u64 wi1p[12][60]        : 5760   (feature columns of w_ih1, packed; init only)
#define OFF_HS    82560    // u64 hs[30][128]         : 30720  (h state, dup-packed per thread)
#define SMEM_BYTES 113280

__global__ __launch_bounds__(128, 2)
void lstm_trace_kernel(const float* __restrict__ features,
                       const float* __restrict__ w_ih1,
                       const float* __restrict__ w_hh1,
                       const float* __restrict__ b1,
                       const float* __restrict__ w_ih2,
                       const float* __restrict__ w_hh2,
                       const float* __restrict__ b2,
                       float* __restrict__ out)
{
    extern __shared__ char smraw[];
    u64*        base2 = (u64*)       (smraw + OFF_BASE2);
    ulonglong2* whh   = (ulonglong2*)(smraw + OFF_WHH);
    u64*        w13p  = (u64*)       (smraw + OFF_W13);
    u64*        wi2p  = (u64*)       (smraw + OFF_WI2);
    u64*        wi1p  = (u64*)       (smraw + OFF_WI1);
    u64*        hs    = (u64*)       (smraw + OFF_HS);

    const int tid = threadIdx.x;
    const int n   = blockIdx.x * 128 + tid;

    // ---- cooperative weight staging (once per block) ----
    for (int e = tid; e < 900; e += 128){
        int k = e / 30, m = e % 30, g0 = 4*m;
        ulonglong2 w;
        w.x = pk2(w_hh1[(g0+0)*30+k], w_hh1[(g0+1)*30+k]);
        w.y = pk2(w_hh1[(g0+2)*30+k], w_hh1[(g0+3)*30+k]);
        whh[k*30+m] = w;
    }
    for (int e = tid; e < 720; e += 128){
        int f = e % 12, jj = e / 12;
        wi1p[f*60+jj] = pk2(w_ih1[(2*jj)*13+f], w_ih1[(2*jj+1)*13+f]);
    }
    if (tid < 60) w13p[tid] = pk2(w_ih1[(2*tid)*13+12], w_ih1[(2*tid+1)*13+12]);
    if (tid < 30){
        wi2p[tid*2+0] = pk2(w_ih2[tid],      w_ih2[30+tid]);
        wi2p[tid*2+1] = pk2(w_ih2[60+tid],   w_ih2[90+tid]);
    }
    __syncthreads();

    // ---- per-sequence time-invariant input projection: base = b1 + W_x * feat(n) ----
    {
        const float4* fp = reinterpret_cast<const float4*>(features) + n*3;
        float4 fa = fp[0], fb = fp[1], fc = fp[2];
        u64 fd[12];
        fd[0]=pk2(fa.x,fa.x); fd[1]=pk2(fa.y,fa.y); fd[2]=pk2(fa.z,fa.z); fd[3]=pk2(fa.w,fa.w);
        fd[4]=pk2(fb.x,fb.x); fd[5]=pk2(fb.y,fb.y); fd[6]=pk2(fb.z,fb.z); fd[7]=pk2(fb.w,fb.w);
        fd[8]=pk2(fc.x,fc.x); fd[9]=pk2(fc.y,fc.y); fd[10]=pk2(fc.z,fc.z); fd[11]=pk2(fc.w,fc.w);
        #pragma unroll
        for (int jj = 0; jj < 60; jj++){
            u64 a = pk2(b1[2*jj], b1[2*jj+1]);
            #pragma unroll
            for (int f = 0; f < 12; f++)
                a = ffma2(wi1p[f*60+jj], fd[f], a);
            base2[jj*128+tid] = a;
        }
    }
    // h0 = 0 (own column only; no sync needed)
    #pragma unroll
    for (int k = 0; k < 30; k++) hs[k*128+tid] = 0ull;

    float c1[30];
    #pragma unroll
    for (int u = 0; u < 30; u++) c1[u] = 0.0f;
    float h2 = 0.0f, c2 = 0.0f;
    const u64 b2p01  = pk2(b2[0], b2[1]),     b2p23  = pk2(b2[2], b2[3]);
    const u64 wh2p01 = pk2(w_hh2[0], w_hh2[1]), wh2p23 = pk2(w_hh2[2], w_hh2[3]);
    float* outp = out + (long long)n * 120;

    // ---- time recurrence ----
    #pragma unroll 1
    for (int t = 0; t < 120; t++){
        const float av  = c_avg[t];
        const u64   av2 = pk2(av, av);

        u64 acc[60];                       // 120 gate pre-activations as 60 packed pairs
        #pragma unroll
        for (int jj = 0; jj < 60; jj++)
            acc[jj] = ffma2(w13p[jj], av2, base2[jj*128+tid]);

        #pragma unroll 3
        for (int k = 0; k < 30; k++){
            const u64 hk = hs[k*128+tid];  // (h[k], h[k])
            const ulonglong2* wr = whh + k*30;
            #pragma unroll
            for (int m = 0; m < 30; m++){
                ulonglong2 w = wr[m];
                acc[2*m]   = ffma2(w.x, hk, acc[2*m]);
                acc[2*m+1] = ffma2(w.y, hk, acc[2*m+1]);
            }
        }

        // layer-2 gate accumulators (4 gates as two packed pairs), recurrent term first
        const u64 h2d = pk2(h2, h2);
        u64 la01 = ffma2(wh2p01, h2d, b2p01);
        u64 la23 = ffma2(wh2p23, h2d, b2p23);

        // LSTM cell update, fused with layer-2 input projection
        #pragma unroll
        for (int p = 0; p < 15; p++){
            float ix,iy,fx,fy,gx,gy,ox,oy;
            up2(acc[p],    ix, iy);
            up2(acc[15+p], fx, fy);
            up2(acc[30+p], gx, gy);
            up2(acc[45+p], ox, oy);
            {
                const int u = 2*p;
                float cc = sigf(fx)*c1[u] + sigf(ix)*tanx(gx);
                c1[u] = cc;
                float h = sigf(ox)*tanx(cc);
                u64 hd = pk2(h,h);
                hs[u*128+tid] = hd;
                la01 = ffma2(wi2p[u*2+0], hd, la01);
                la23 = ffma2(wi2p[u*2+1], hd, la23);
            }
            {
                const int u = 2*p+1;
                float cc = sigf(fy)*c1[u] + sigf(iy)*tanx(gy);
                c1[u] = cc;
                float h = sigf(oy)*tanx(cc);
                u64 hd = pk2(h,h);
                hs[u*128+tid] = hd;
                la01 = ffma2(wi2p[u*2+0], hd, la01);
                la23 = ffma2(wi2p[u*2+1], hd, la23);
            }
        }

        float gi,gf,gg,go;
        up2(la01, gi, gf);
        up2(la23, gg, go);
        c2 = sigf(gf)*c2 + sigf(gi)*tanx(gg);
        h2 = sigf(go)*tanx(c2);
        outp[t] = h2;
    }
}

extern "C" void kernel_launch(void* const* d_in, const int* in_sizes, int n_in,
                              void* d_out, int out_size)
{
    const float* features = (const float*)d_in[0];
    const float* w_ih1    = (const float*)d_in[1];
    const float* w_hh1    = (const float*)d_in[2];
    const float* b1       = (const float*)d_in[3];
    const float* w_ih2    = (const float*)d_in[4];
    const float* w_hh2    = (const float*)d_in[5];
    const float* b2       = (const float*)d_in[6];
    float* out = (float*)d_out;

    cudaFuncSetAttribute(lstm_trace_kernel,
                         cudaFuncAttributeMaxDynamicSharedMemorySize, SMEM_BYTES);
    lstm_trace_kernel<<<256, 128, SMEM_BYTES>>>(features, w_ih1, w_hh1, b1,
                                                w_ih2, w_hh2, b2, out);
}

// round 5
// speedup vs baseline: 1.5061x; 1.5061x over previous
#include <cuda_runtime.h>

typedef unsigned long long u64;
#define DI __device__ __forceinline__

// Fixed average-trace buffer (length 120) from the reference module
__constant__ float c_avg[120] = {
 0.0256f,0.0823f,0.1157f,0.1315f,0.1366f,0.1369f,0.1347f,0.1308f,0.1259f,0.1205f,
 0.1146f,0.1086f,0.1028f,0.0970f,0.0913f,0.0858f,0.0805f,0.0756f,0.0708f,0.0664f,
 0.0623f,0.0584f,0.0549f,0.0515f,0.0485f,0.0456f,0.0429f,0.0404f,0.0381f,0.0360f,
 0.0340f,0.0321f,0.0304f,0.0287f,0.0272f,0.0258f,0.0245f,0.0233f,0.0222f,0.0211f,
 0.0201f,0.0191f,0.0182f,0.0173f,0.0165f,0.0158f,0.0150f,0.0143f,0.0137f,0.0130f,
 0.0125f,0.0119f,0.0114f,0.0108f,0.0104f,0.0099f,0.0095f,0.0091f,0.0087f,0.0083f,
 0.0080f,0.0077f,0.0074f,0.0071f,0.0068f,0.0065f,0.0062f,0.0060f,0.0058f,0.0055f,
 0.0053f,0.0050f,0.0049f,0.0047f,0.0045f,0.0044f,0.0042f,0.0040f,0.0039f,0.0038f,
 0.0036f,0.0034f,0.0033f,0.0032f,0.0031f,0.0030f,0.0029f,0.0028f,0.0027f,0.0026f,
 0.0025f,0.0024f,0.0023f,0.0022f,0.0021f,0.0021f,0.0020f,0.0019f,0.0018f,0.0018f,
 0.0017f,0.0017f,0.0016f,0.0016f,0.0015f,0.0015f,0.0014f,0.0014f,0.0013f,0.0013f,
 0.0013f,0.0012f,0.0012f,0.0011f,0.0011f,0.0011f,0.0010f,0.0010f,0.0010f,0.0009f
};

DI u64 pk2(float lo, float hi){ u64 r; asm("mov.b64 %0, {%1,%2};" : "=l"(r) : "f"(lo), "f"(hi)); return r; }
DI void up2(u64 v, float& lo, float& hi){ asm("mov.b64 {%0,%1}, %2;" : "=f"(lo), "=f"(hi) : "l"(v)); }
DI u64 ffma2(u64 a, u64 b, u64 c){ u64 d; asm("fma.rn.f32x2 %0, %1, %2, %3;" : "=l"(d) : "l"(a), "l"(b), "l"(c)); return d; }
DI u64 fmul2(u64 a, u64 b){ u64 d; asm("mul.rn.f32x2 %0, %1, %2;" : "=l"(d) : "l"(a), "l"(b)); return d; }
DI float sigf(float x){ return __fdividef(1.0f, 1.0f + __expf(-x)); }
DI float tanx(float x){ float t = __expf(-2.0f*x); return __fdividef(1.0f - t, 1.0f + t); }
DI float hadd2(u64 v){ float lo, hi; up2(v, lo, hi); return lo + hi; }

// Shared memory layout (bytes). 64 sequences per block, 2 threads/seq.
// Row index r = half*15 + j  ->  unit u = 2*j + half.
#define OFF_WIF  0        // ulonglong2 wIF[30][15] : 7200  ({i,f}-gate weight pairs along k)
#define OFF_WGO  7200     // ulonglong2 wGO[30][15] : 7200  ({g,o}-gate weight pairs along k)
#define OFF_BASE 14400    // float4 baseS[15][128]  : 30720 (per-thread: 4-gate base per local unit)
#define OFF_W13  45120    // float4 w13S[15][2]     : 480   (trace-channel weights, 4 gates per unit)
#define OFF_W2   45600    // u64 w2S[4][15]         : 480   (layer-2 input weights, k-packed)
#define SMEM_BYTES 46080

__global__ __launch_bounds__(128, 4)
void lstm_trace_kernel(const float* __restrict__ features,
                       const float* __restrict__ w_ih1,
                       const float* __restrict__ w_hh1,
                       const float* __restrict__ b1,
                       const float* __restrict__ w_ih2,
                       const float* __restrict__ w_hh2,
                       const float* __restrict__ b2,
                       float* __restrict__ out)
{
    extern __shared__ char smraw[];
    ulonglong2* wIF   = (ulonglong2*)(smraw + OFF_WIF);
    ulonglong2* wGO   = (ulonglong2*)(smraw + OFF_WGO);
    float4*     baseS = (float4*)    (smraw + OFF_BASE);
    float4*     w13S  = (float4*)    (smraw + OFF_W13);
    u64*        w2S   = (u64*)       (smraw + OFF_W2);

    const int tid  = threadIdx.x;
    const int half = tid & 1;                    // 0: even units, 1: odd units
    const int seq  = blockIdx.x * 64 + (tid >> 1);

    // ---- stage recurrent weight tables (k-packed pairs) ----
    for (int e = tid; e < 450; e += 128){
        int r  = e / 15, k2 = e % 15;
        int u  = (r < 15) ? 2*r : 2*(r-15) + 1;
        int c0 = 2*k2, c1 = 2*k2 + 1;
        ulonglong2 a, b;
        a.x = pk2(w_hh1[      u *30 + c0], w_hh1[      u *30 + c1]);
        a.y = pk2(w_hh1[(30 + u)*30 + c0], w_hh1[(30 + u)*30 + c1]);
        b.x = pk2(w_hh1[(60 + u)*30 + c0], w_hh1[(60 + u)*30 + c1]);
        b.y = pk2(w_hh1[(90 + u)*30 + c0], w_hh1[(90 + u)*30 + c1]);
        wIF[e] = a; wGO[e] = b;
    }
    if (tid < 30){
        int j = tid >> 1, hh = tid & 1, u = 2*j + hh;
        float4 v;
        v.x = w_ih1[      u *13 + 12];
        v.y = w_ih1[(30 + u)*13 + 12];
        v.z = w_ih1[(60 + u)*13 + 12];
        v.w = w_ih1[(90 + u)*13 + 12];
        w13S[j*2 + hh] = v;
    }
    if (tid < 60){
        int g = tid / 15, k2 = tid % 15;
        w2S[tid] = pk2(w_ih2[g*30 + 2*k2], w_ih2[g*30 + 2*k2 + 1]);
    }

    // ---- per-thread time-invariant base: b1 + W_x * feat (own 15 units x 4 gates) ----
    {
        float f[12];
        const float4* fp = reinterpret_cast<const float4*>(features) + (size_t)seq * 3;
        float4 fa = fp[0], fb = fp[1], fc = fp[2];
        f[0]=fa.x; f[1]=fa.y; f[2]=fa.z; f[3]=fa.w;
        f[4]=fb.x; f[5]=fb.y; f[6]=fb.z; f[7]=fb.w;
        f[8]=fc.x; f[9]=fc.y; f[10]=fc.z; f[11]=fc.w;
        #pragma unroll
        for (int j = 0; j < 15; j++){
            int u = 2*j + half;
            float4 bs;
            float* bsv = &bs.x;
            #pragma unroll
            for (int g = 0; g < 4; g++){
                int row = g*30 + u;
                float s = __ldg(&b1[row]);
                #pragma unroll
                for (int ff = 0; ff < 12; ff++)
                    s = fmaf(__ldg(&w_ih1[row*13 + ff]), f[ff], s);
                bsv[g] = s;
            }
            baseS[j*128 + tid] = bs;
        }
    }
    __syncthreads();

    // ---- per-thread recurrent state ----
    u64   hpk[15];                // (h[2j], h[2j+1]) — full layer-1 h, both threads
    float c1v[15];                // cell state for OWN 15 units
    #pragma unroll
    for (int j = 0; j < 15; j++){ hpk[j] = 0ull; c1v[j] = 0.0f; }
    float h2 = 0.0f, c2 = 0.0f;
    const float b2r0 = b2[0], b2r1 = b2[1], b2r2 = b2[2], b2r3 = b2[3];
    const float wh20 = w_hh2[0], wh21 = w_hh2[1], wh22 = w_hh2[2], wh23 = w_hh2[3];
    float* outp = out + (size_t)seq * 120;

    const ulonglong2* myWIF  = wIF + (half*15) * 15;
    const ulonglong2* myWGO  = wGO + (half*15) * 15;
    const float4*     myBase = baseS + tid;      // [j*128]
    const float4*     myW13  = w13S + half;      // [j*2]

    // ---- time recurrence ----
    #pragma unroll 1
    for (int t = 0; t < 120; t++){
        const float av = c_avg[t];
        float newh[15];

        #pragma unroll 5
        for (int j = 0; j < 15; j++){
            const ulonglong2* wif = myWIF + j*15;
            const ulonglong2* wgo = myWGO + j*15;
            u64 ai, af, ag, ao;
            {
                ulonglong2 a = wif[0], b = wgo[0];
                ai = fmul2(a.x, hpk[0]); af = fmul2(a.y, hpk[0]);
                ag = fmul2(b.x, hpk[0]); ao = fmul2(b.y, hpk[0]);
            }
            #pragma unroll
            for (int k2 = 1; k2 < 15; k2++){
                ulonglong2 a = wif[k2], b = wgo[k2];
                ai = ffma2(a.x, hpk[k2], ai); af = ffma2(a.y, hpk[k2], af);
                ag = ffma2(b.x, hpk[k2], ag); ao = ffma2(b.y, hpk[k2], ao);
            }
            float4 bs  = myBase[j*128];
            float4 w13 = myW13[j*2];
            float gi = fmaf(w13.x, av, hadd2(ai) + bs.x);
            float gf = fmaf(w13.y, av, hadd2(af) + bs.y);
            float gg = fmaf(w13.z, av, hadd2(ag) + bs.z);
            float go = fmaf(w13.w, av, hadd2(ao) + bs.w);

            float cc = sigf(gf) * c1v[j] + sigf(gi) * tanx(gg);
            c1v[j]  = cc;
            newh[j] = sigf(go) * tanx(cc);
        }

        // exchange new h with partner thread, repack as (even, odd) pairs
        #pragma unroll
        for (int j = 0; j < 15; j++){
            float other = __shfl_xor_sync(0xFFFFFFFFu, newh[j], 1);
            float ev = half ? other   : newh[j];
            float od = half ? newh[j] : other;
            hpk[j] = pk2(ev, od);
        }

        // layer 2 (computed redundantly by both threads of the pair)
        u64 a0 = fmul2(w2S[0],  hpk[0]);
        u64 a1 = fmul2(w2S[15], hpk[0]);
        u64 a2 = fmul2(w2S[30], hpk[0]);
        u64 a3 = fmul2(w2S[45], hpk[0]);
        #pragma unroll
        for (int k2 = 1; k2 < 15; k2++){
            a0 = ffma2(w2S[k2],      hpk[k2], a0);
            a1 = ffma2(w2S[15 + k2], hpk[k2], a1);
            a2 = ffma2(w2S[30 + k2], hpk[k2], a2);
            a3 = ffma2(w2S[45 + k2], hpk[k2], a3);
        }
        float i2 = hadd2(a0) + b2r0 + wh20 * h2;
        float f2 = hadd2(a1) + b2r1 + wh21 * h2;
        float g2 = hadd2(a2) + b2r2 + wh22 * h2;
        float o2 = hadd2(a3) + b2r3 + wh23 * h2;
        c2 = sigf(f2) * c2 + sigf(i2) * tanx(g2);
        h2 = sigf(o2) * tanx(c2);

        if (!half) outp[t] = h2;
    }
}

extern "C" void kernel_launch(void* const* d_in, const int* in_sizes, int n_in,
                              void* d_out, int out_size)
{
    const float* features = (const float*)d_in[0];
    const float* w_ih1    = (const float*)d_in[1];
    const float* w_hh1    = (const float*)d_in[2];
    const float* b1       = (const float*)d_in[3];
    const float* w_ih2    = (const float*)d_in[4];
    const float* w_hh2    = (const float*)d_in[5];
    const float* b2       = (const float*)d_in[6];
    float* out = (float*)d_out;

    cudaFuncSetAttribute(lstm_trace_kernel,
                         cudaFuncAttributeMaxDynamicSharedMemorySize, SMEM_BYTES);
    lstm_trace_kernel<<<512, 128, SMEM_BYTES>>>(features, w_ih1, w_hh1, b1,
                                                w_ih2, w_hh2, b2, out);
}